// round 10
// baseline (speedup 1.0000x reference)
#include <cuda_runtime.h>
#include <cuda_bf16.h>

typedef unsigned long long ull;

#define GMM_M   64
#define GMM_D   16
#define GMM_KP  8      // 16 dims = 8 f32x2 pairs
#define TPB     128
#define PPT     2
#define PPB     (TPB*PPT)

__device__ float4   g_P[GMM_M * GMM_KP];  // {A2k,A2k+1,B2k,B2k+1}, log2e-folded
__device__ float    g_C[GMM_M];           // log2e-folded constant
__device__ float    g_part[8192];
__device__ unsigned g_count = 0;

__device__ __forceinline__ ull pk2(float lo, float hi) {
    ull r; asm("mov.b64 %0, {%1, %2};" : "=l"(r) : "f"(lo), "f"(hi)); return r;
}
__device__ __forceinline__ void upk2(ull v, float &lo, float &hi) {
    asm("mov.b64 {%0, %1}, %2;" : "=f"(lo), "=f"(hi) : "l"(v));
}
__device__ __forceinline__ ull fma2(ull a, ull b, ull c) {
    ull r; asm("fma.rn.f32x2 %0, %1, %2, %3;" : "=l"(r) : "l"(a), "l"(b), "l"(c)); return r;
}
__device__ __forceinline__ ull add2(ull a, ull b) {
    ull r; asm("add.rn.f32x2 %0, %1, %2;" : "=l"(r) : "l"(a), "l"(b)); return r;
}
__device__ __forceinline__ float ex2f(float x) {
    float r; asm("ex2.approx.f32 %0, %1;" : "=f"(r) : "f"(x)); return r;
}

// ---------- kernel 1: parameter precompute (log2e folded) ----------
__global__ void __launch_bounds__(1024)
gmm_precompute(const float* __restrict__ wghts,
               const float* __restrict__ means,
               const float* __restrict__ dcovs) {
    __shared__ float sAf[GMM_M][GMM_D];
    __shared__ float sBf[GMM_M][GMM_D];
    const int tid = threadIdx.x;
    const int m = tid >> 4;
    const int d = tid & 15;
    const float LOG2E = 1.4426950408889634f;

    const float dc   = dcovs[m * GMM_D + d];
    const float mu   = means[m * GMM_D + d];
    const float prec = 1.0f / dc;
    sAf[m][d] = -0.5f * prec * LOG2E;
    sBf[m][d] = prec * mu * LOG2E;

    float cpart = (-0.5f * prec * mu * mu - 0.5f * __logf(dc)) * LOG2E;
    #pragma unroll
    for (int o = 8; o > 0; o >>= 1)
        cpart += __shfl_down_sync(0xffffffffu, cpart, o, 16);
    if (d == 0)
        g_C[m] = cpart + (__logf(wghts[m]) - 8.0f * __logf(6.283185307f)) * LOG2E;

    __syncthreads();
    if (tid < GMM_M * GMM_KP) {
        const int pm = tid >> 3;
        const int k  = tid & 7;
        g_P[tid] = make_float4(sAf[pm][2*k], sAf[pm][2*k+1],
                               sBf[pm][2*k], sBf[pm][2*k+1]);
    }
}

// ---------- kernel 2: main GMM E-step (non-persistent, 5 blocks/SM) ----------
__global__ void __launch_bounds__(TPB, 5)
gmm_main(const float* __restrict__ data,
         const float* __restrict__ means,
         float* __restrict__ out,
         int T, float invT) {
    __shared__ ulonglong2 sP[GMM_M * GMM_KP];
    __shared__ ulonglong2 sMu[GMM_M * 4];
    __shared__ float      sC[GMM_M];
    __shared__ float      sStage[PPB * 17];   // pitch-17 transpose, both points
    __shared__ float      sRed[TPB];
    __shared__ bool       sLast;

    const int tid = threadIdx.x;
    {
        const float4* gp = (const float4*)g_P;
        float4*       dp = (float4*)sP;
        for (int i = tid; i < GMM_M * GMM_KP; i += TPB) dp[i] = gp[i];
        const float4* gm = (const float4*)means;
        float4*       dm = (float4*)sMu;
        for (int i = tid; i < GMM_M * 4; i += TPB) dm[i] = gm[i];
        if (tid < GMM_M) sC[tid] = g_C[tid];
    }
    __syncthreads();

    const int base = blockIdx.x * PPB;

    ull x[PPT][GMM_KP], num[PPT][GMM_KP];
    float like[PPT];

    #pragma unroll
    for (int j = 0; j < PPT; j++) {
        like[j] = 0.0f;
        const int t = base + tid + j * TPB;
        if (t < T) {
            const ulonglong2* dp2 = (const ulonglong2*)(data + (size_t)t * GMM_D);
            #pragma unroll
            for (int q = 0; q < 4; q++) {
                const ulonglong2 f = dp2[q];   // LDG.128, no repack
                x[j][2*q]   = f.x;
                x[j][2*q+1] = f.y;
            }
        } else {
            #pragma unroll
            for (int k = 0; k < GMM_KP; k++) x[j][k] = 0ULL;
        }
        #pragma unroll
        for (int k = 0; k < GMM_KP; k++) num[j][k] = 0ULL;
    }

    #pragma unroll 4
    for (int m = 0; m < GMM_M; m++) {
        // two independent accumulator chains per point; c added at the END so
        // the sC load overlaps the whole chain instead of gating its start
        ull acc0[PPT], acc1[PPT];
        #pragma unroll
        for (int j = 0; j < PPT; j++) { acc0[j] = 0ULL; acc1[j] = 0ULL; }

        const float c = sC[m];   // LDS.32, independent of chain below

        #pragma unroll
        for (int k = 0; k < 4; k++) {
            const ulonglong2 abL = sP[m * GMM_KP + k];       // LDS.128 broadcast
            const ulonglong2 abH = sP[m * GMM_KP + k + 4];
            #pragma unroll
            for (int j = 0; j < PPT; j++) {
                const ull t0 = fma2(abL.x, x[j][k], abL.y);
                acc0[j] = fma2(t0, x[j][k], acc0[j]);
                const ull t1 = fma2(abH.x, x[j][k + 4], abH.y);
                acc1[j] = fma2(t1, x[j][k + 4], acc1[j]);
            }
        }

        ull pb[PPT];
        #pragma unroll
        for (int j = 0; j < PPT; j++) {
            const ull acc = add2(acc0[j], acc1[j]);
            float lo, hi;
            upk2(acc, lo, hi);
            const float p = ex2f(lo + hi + c);
            like[j] += p;
            pb[j] = pk2(p, p);
        }

        #pragma unroll
        for (int kk = 0; kk < 4; kk++) {
            const ulonglong2 mm = sMu[m * 4 + kk];
            #pragma unroll
            for (int j = 0; j < PPT; j++) {
                num[j][2*kk]   = fma2(pb[j], mm.x, num[j][2*kk]);
                num[j][2*kk+1] = fma2(pb[j], mm.y, num[j][2*kk+1]);
            }
        }
    }

    float llsum = 0.0f;

    // epilogue: single-pass SMEM transpose for both points -> coalesced STG.32
    #pragma unroll
    for (int j = 0; j < PPT; j++) {
        const int tj = base + tid + j * TPB;
        const bool valid = (tj < T);
        const float inv = valid ? __fdividef(1.0f, like[j]) : 0.0f;
        if (valid) llsum += __logf(like[j]);

        const int row = tid + j * TPB;
        #pragma unroll
        for (int k = 0; k < GMM_KP; k++) {
            float f0, f1;
            upk2(num[j][k], f0, f1);
            sStage[row * 17 + 2*k]     = f0 * inv;
            sStage[row * 17 + 2*k + 1] = f1 * inv;
        }
    }
    __syncthreads();
    {
        float* op = out + 1 + (size_t)base * GMM_D;
        const int limit = min(PPB, T - base) * GMM_D;
        for (int i = tid; i < limit; i += TPB)
            op[i] = sStage[(i >> 4) * 17 + (i & 15)];
    }

    // deterministic block reduction of log-likes
    sRed[tid] = llsum;
    __syncthreads();
    #pragma unroll
    for (int s = TPB / 2; s > 0; s >>= 1) {
        if (tid < s) sRed[tid] += sRed[tid + s];
        __syncthreads();
    }
    if (tid == 0) {
        g_part[blockIdx.x] = sRed[0];
        __threadfence();
        unsigned old = atomicAdd(&g_count, 1u);
        sLast = (old == (unsigned)(gridDim.x - 1));
    }
    __syncthreads();

    if (sLast) {
        __threadfence();
        float acc2 = 0.0f;
        for (int i = tid; i < (int)gridDim.x; i += TPB) acc2 += g_part[i];
        sRed[tid] = acc2;
        __syncthreads();
        #pragma unroll
        for (int s = TPB / 2; s > 0; s >>= 1) {
            if (tid < s) sRed[tid] += sRed[tid + s];
            __syncthreads();
        }
        if (tid == 0) {
            out[0] = sRed[0] * invT;
            g_count = 0;
        }
    }
}

extern "C" void kernel_launch(void* const* d_in, const int* in_sizes, int n_in,
                              void* d_out, int out_size) {
    const float* data  = (const float*)d_in[0];
    const float* wghts = (const float*)d_in[1];
    const float* means = (const float*)d_in[2];
    const float* dcovs = (const float*)d_in[3];
    float* out = (float*)d_out;

    const int T = in_sizes[0] / GMM_D;
    const int grid = (T + PPB - 1) / PPB;   // non-persistent: HW backfills

    gmm_precompute<<<1, 1024>>>(wghts, means, dcovs);
    gmm_main<<<grid, TPB>>>(data, means, out, T, 1.0f / (float)T);
}

// round 13
// speedup vs baseline: 1.1083x; 1.1083x over previous
#include <cuda_runtime.h>
#include <cuda_fp16.h>
#include <cstdint>

#define GMM_M  64
#define GMM_D  16
#define TPB    128
#define PPB    128
#define PF     136              // half pitch (17 x 16B -> ldmatrix conflict-free)
#define PFB    272              // bytes

// dynamic SMEM layout
#define OFF_W1 0                               // [64][PF] fp16  = 17408 B
#define OFF_W2 17408                           // [24][PF] fp16  = 6528 B
#define OFF_F  23936                           // [128][PF] fp16 = 34816 B
#define OFF_STG OFF_F                          // f32[128*17] overlays F after stage1
#define DSMEM  58752

#define LOG2E  1.4426950408889634f
#define LN2F   0.6931471805599453f

__device__ __align__(16) __half g_W1h[GMM_M * PF];
__device__ __align__(16) __half g_W2h[24 * PF];
__device__ float    g_part[8192];
__device__ unsigned g_count = 0;

// ---------------- helpers ----------------
__device__ __forceinline__ uint32_t smem_u32(const void* p) {
    uint32_t a;
    asm("{ .reg .u64 t; cvta.to.shared.u64 t, %1; cvt.u32.u64 %0, t; }" : "=r"(a) : "l"(p));
    return a;
}
__device__ __forceinline__ float ex2f(float x) {
    float r; asm("ex2.approx.f32 %0, %1;" : "=f"(r) : "f"(x)); return r;
}
__device__ __forceinline__ uint32_t h2u(__half2 h) { return *reinterpret_cast<uint32_t*>(&h); }

__device__ __forceinline__ void ldsm4(uint32_t* r, uint32_t addr) {
    asm volatile("ldmatrix.sync.aligned.m8n8.x4.shared.b16 {%0,%1,%2,%3}, [%4];"
        : "=r"(r[0]), "=r"(r[1]), "=r"(r[2]), "=r"(r[3]) : "r"(addr));
}
__device__ __forceinline__ void ldsm2(uint32_t* r, uint32_t addr) {
    asm volatile("ldmatrix.sync.aligned.m8n8.x2.shared.b16 {%0,%1}, [%2];"
        : "=r"(r[0]), "=r"(r[1]) : "r"(addr));
}
__device__ __forceinline__ void mma16816(float* d, const uint32_t* a, const uint32_t* b) {
    asm volatile("mma.sync.aligned.m16n8k16.row.col.f32.f16.f16.f32 "
        "{%0,%1,%2,%3}, {%4,%5,%6,%7}, {%8,%9}, {%0,%1,%2,%3};"
        : "+f"(d[0]), "+f"(d[1]), "+f"(d[2]), "+f"(d[3])
        : "r"(a[0]), "r"(a[1]), "r"(a[2]), "r"(a[3]), "r"(b[0]), "r"(b[1]));
}

// ---------------- kernel 1: build fp16 W images ----------------
__global__ void __launch_bounds__(1024)
gmm_precompute(const float* __restrict__ wghts,
               const float* __restrict__ means,
               const float* __restrict__ dcovs) {
    const int tid = threadIdx.x;
    const __half hz = __float2half_rn(0.0f);
    for (int i = tid; i < GMM_M * PF; i += 1024) g_W1h[i] = hz;
    for (int i = tid; i < 24 * PF; i += 1024)    g_W2h[i] = hz;
    __syncthreads();

    const int m = tid >> 4;
    const int d = tid & 15;

    const float dc   = dcovs[m * GMM_D + d];
    const float mu   = means[m * GMM_D + d];
    const float prec = 1.0f / dc;
    const float A = -0.5f * prec * LOG2E;
    const float B = prec * mu * LOG2E;

    float cpart = (-0.5f * prec * mu * mu - 0.5f * __logf(dc)) * LOG2E;
    #pragma unroll
    for (int o = 8; o > 0; o >>= 1)
        cpart += __shfl_down_sync(0xffffffffu, cpart, o, 16);

    const __half Ah = __float2half_rn(A);
    const __half Al = __float2half_rn(A - __half2float(Ah));
    const __half Bh = __float2half_rn(B);
    const __half Bl = __float2half_rn(B - __half2float(Bh));

    __half* w1 = g_W1h + m * PF;
    w1[d]      = Ah;  w1[16 + d] = Bh;
    w1[40 + d] = Al;  w1[56 + d] = Bl;
    w1[80 + d] = Ah;  w1[96 + d] = Bh;

    if (d == 0) {
        const float C = cpart + (__logf(wghts[m]) - 8.0f * __logf(6.283185307f)) * LOG2E;
        const __half Ch = __float2half_rn(C);
        const __half Cl = __float2half_rn(C - __half2float(Ch));
        w1[32] = Ch;
        w1[72] = Cl;
    }

    const __half muh = __float2half_rn(mu);
    g_W2h[d * PF + m]      = muh;
    g_W2h[d * PF + 64 + m] = muh;
    if (tid < 128) g_W2h[16 * PF + tid] = __float2half_rn(1.0f);   // likes row
}

// ---------------- kernel 2: fp16 mma.sync GMM E-step ----------------
__global__ void __launch_bounds__(TPB)
gmm_main(const float* __restrict__ data,
         float* __restrict__ out,
         int T, float invT) {
    extern __shared__ __align__(16) char dsm[];
    __shared__ float sRed[TPB];
    __shared__ bool  sLast;

    const int tid  = threadIdx.x;
    const int lane = tid & 31;
    const int wid  = tid >> 5;
    const uint32_t sb = smem_u32(dsm);

    // copy W images into SMEM
    {
        const float4* s1 = (const float4*)g_W1h;
        float4*       d1 = (float4*)(dsm + OFF_W1);
        for (int i = tid; i < (GMM_M * PF * 2) / 16; i += TPB) d1[i] = s1[i];
        const float4* s2 = (const float4*)g_W2h;
        float4*       d2 = (float4*)(dsm + OFF_W2);
        for (int i = tid; i < (24 * PF * 2) / 16; i += TPB) d2[i] = s2[i];
    }

    // features for my point -> F row (fp16, error-split)
    const int  base  = blockIdx.x * PPB;
    const int  tglob = base + tid;
    const bool valid = (tglob < T);
    float xv[GMM_D];
    if (valid) {
        const float4* dp = (const float4*)(data + (size_t)tglob * GMM_D);
        #pragma unroll
        for (int q = 0; q < 4; q++) {
            const float4 f = dp[q];
            xv[4*q] = f.x; xv[4*q+1] = f.y; xv[4*q+2] = f.z; xv[4*q+3] = f.w;
        }
    } else {
        #pragma unroll
        for (int d = 0; d < GMM_D; d++) xv[d] = 0.0f;
    }
    {
        uint32_t row[68];
        #pragma unroll
        for (int j = 0; j < 68; j++) row[j] = 0u;
        #pragma unroll
        for (int q = 0; q < 8; q++) {
            const float u0 = xv[2*q] * xv[2*q], u1 = xv[2*q+1] * xv[2*q+1];
            const __half2 uh2 = __floats2half2_rn(u0, u1);
            const __half2 ul2 = __floats2half2_rn(u0 - __low2float(uh2), u1 - __high2float(uh2));
            const __half2 vh2 = __floats2half2_rn(xv[2*q], xv[2*q+1]);
            const __half2 vl2 = __floats2half2_rn(xv[2*q] - __low2float(vh2), xv[2*q+1] - __high2float(vh2));
            row[q]      = h2u(uh2);  row[20 + q] = h2u(uh2);
            row[8 + q]  = h2u(vh2);  row[28 + q] = h2u(vh2);
            row[40 + q] = h2u(ul2);  row[48 + q] = h2u(vl2);
        }
        row[16] = 0x00003c00u;   // 1.0h (C hi slot)
        row[36] = 0x00003c00u;   // 1.0h (C lo slot)
        uint4* fr = (uint4*)(dsm + OFF_F + tid * PFB);
        #pragma unroll
        for (int q = 0; q < 17; q++)
            fr[q] = make_uint4(row[4*q], row[4*q+1], row[4*q+2], row[4*q+3]);
    }
    __syncthreads();

    // ---------------- stage 1: E = F * W1^T ----------------
    float acc[2][8][4];
    #pragma unroll
    for (int mt = 0; mt < 2; mt++)
        #pragma unroll
        for (int nt = 0; nt < 8; nt++)
            #pragma unroll
            for (int i = 0; i < 4; i++) acc[mt][nt][i] = 0.0f;

    const uint32_t fb  = sb + OFF_F;
    const uint32_t w1b = sb + OFF_W1;
    const int rselA = lane & 15;                    // A: row within 16-tile
    const uint32_t koffA = (lane >> 4) * 16;        // A: k-half byte offset
    const int nrowB = (lane & 7) + ((lane & 16) ? 8 : 0);
    const uint32_t koffB = (lane & 8) ? 16u : 0u;

    #pragma unroll
    for (int ks = 0; ks < 8; ks++) {
        uint32_t aF[2][4];
        #pragma unroll
        for (int mt = 0; mt < 2; mt++)
            ldsm4(aF[mt], fb + (wid * 32 + mt * 16 + rselA) * PFB + ks * 32 + koffA);

        uint32_t bW[8][2];
        #pragma unroll
        for (int p = 0; p < 4; p++) {
            uint32_t r[4];
            ldsm4(r, w1b + (p * 16 + nrowB) * PFB + ks * 32 + koffB);
            bW[2*p][0]   = r[0]; bW[2*p][1]   = r[1];
            bW[2*p+1][0] = r[2]; bW[2*p+1][1] = r[3];
        }
        #pragma unroll
        for (int nt = 0; nt < 8; nt++)
            #pragma unroll
            for (int mt = 0; mt < 2; mt++)
                mma16816(acc[mt][nt], aF[mt], bW[nt]);
    }

    // ---------------- row-max, exp2, pack p' hi/lo ----------------
    float rA[2], rB[2];
    uint32_t pH[2][8][2], pL[2][8][2];
    #pragma unroll
    for (int mt = 0; mt < 2; mt++) {
        float mg = -1e30f, mg8 = -1e30f;
        #pragma unroll
        for (int nt = 0; nt < 8; nt++) {
            mg  = fmaxf(mg,  fmaxf(acc[mt][nt][0], acc[mt][nt][1]));
            mg8 = fmaxf(mg8, fmaxf(acc[mt][nt][2], acc[mt][nt][3]));
        }
        mg  = fmaxf(mg,  __shfl_xor_sync(0xffffffffu, mg, 1));
        mg  = fmaxf(mg,  __shfl_xor_sync(0xffffffffu, mg, 2));
        mg8 = fmaxf(mg8, __shfl_xor_sync(0xffffffffu, mg8, 1));
        mg8 = fmaxf(mg8, __shfl_xor_sync(0xffffffffu, mg8, 2));
        rA[mt] = mg; rB[mt] = mg8;
        #pragma unroll
        for (int nt = 0; nt < 8; nt++) {
            const float p0 = ex2f(acc[mt][nt][0] - mg);
            const float p1 = ex2f(acc[mt][nt][1] - mg);
            const float p2 = ex2f(acc[mt][nt][2] - mg8);
            const float p3 = ex2f(acc[mt][nt][3] - mg8);
            const __half2 h01 = __floats2half2_rn(p0, p1);
            const __half2 h23 = __floats2half2_rn(p2, p3);
            pH[mt][nt][0] = h2u(h01);
            pH[mt][nt][1] = h2u(h23);
            pL[mt][nt][0] = h2u(__floats2half2_rn(p0 - __low2float(h01), p1 - __high2float(h01)));
            pL[mt][nt][1] = h2u(__floats2half2_rn(p2 - __low2float(h23), p3 - __high2float(h23)));
        }
    }

    // ---------------- stage 2: [num | like] = P' * W2^T ----------------
    float acc2[2][3][4];
    #pragma unroll
    for (int mt = 0; mt < 2; mt++)
        #pragma unroll
        for (int nt = 0; nt < 3; nt++)
            #pragma unroll
            for (int i = 0; i < 4; i++) acc2[mt][nt][i] = 0.0f;

    const uint32_t w2b = sb + OFF_W2;
    #pragma unroll
    for (int ks2 = 0; ks2 < 8; ks2++) {
        uint32_t bW2[3][2];
        {
            uint32_t r[4];
            ldsm4(r, w2b + nrowB * PFB + ks2 * 32 + koffB);            // ntiles 0,1
            bW2[0][0] = r[0]; bW2[0][1] = r[1];
            bW2[1][0] = r[2]; bW2[1][1] = r[3];
            uint32_t r2[2];
            ldsm2(r2, w2b + (16 + (lane & 7)) * PFB + ks2 * 32 + koffB); // ntile 2
            bW2[2][0] = r2[0]; bW2[2][1] = r2[1];
        }
        const int nt2 = 2 * (ks2 & 3);
        #pragma unroll
        for (int mt = 0; mt < 2; mt++) {
            uint32_t a2[4];
            if (ks2 < 4) {
                a2[0] = pH[mt][nt2][0];   a2[1] = pH[mt][nt2][1];
                a2[2] = pH[mt][nt2+1][0]; a2[3] = pH[mt][nt2+1][1];
            } else {
                a2[0] = pL[mt][nt2][0];   a2[1] = pL[mt][nt2][1];
                a2[2] = pL[mt][nt2+1][0]; a2[3] = pL[mt][nt2+1][1];
            }
            #pragma unroll
            for (int nt = 0; nt < 3; nt++)
                mma16816(acc2[mt][nt], a2, bW2[nt]);
        }
    }

    // ---------------- epilogue: posteriors, stage, log-likes ----------------
    __syncthreads();    // all warps done reading F -> safe to overlay stg
    float* stg = (float*)(dsm + OFF_STG);
    const int g = lane >> 2, t = lane & 3;
    float llsum = 0.0f;

    #pragma unroll
    for (int mt = 0; mt < 2; mt++) {
        const float likeg  = __shfl_sync(0xffffffffu, acc2[mt][2][0], lane & ~3);
        const float likeg8 = __shfl_sync(0xffffffffu, acc2[mt][2][2], lane & ~3);
        const float invg  = __fdividef(1.0f, likeg);
        const float invg8 = __fdividef(1.0f, likeg8);
        const int r  = wid * 32 + mt * 16 + g;
        stg[r * 17 + 2*t]     = acc2[mt][0][0] * invg;
        stg[r * 17 + 2*t + 1] = acc2[mt][0][1] * invg;
        stg[r * 17 + 8 + 2*t] = acc2[mt][1][0] * invg;
        stg[r * 17 + 9 + 2*t] = acc2[mt][1][1] * invg;
        stg[(r+8) * 17 + 2*t]     = acc2[mt][0][2] * invg8;
        stg[(r+8) * 17 + 2*t + 1] = acc2[mt][0][3] * invg8;
        stg[(r+8) * 17 + 8 + 2*t] = acc2[mt][1][2] * invg8;
        stg[(r+8) * 17 + 9 + 2*t] = acc2[mt][1][3] * invg8;
        if (t == 0) {
            if (base + r < T)     llsum += __logf(likeg)  + rA[mt] * LN2F;
            if (base + r + 8 < T) llsum += __logf(likeg8) + rB[mt] * LN2F;
        }
    }
    __syncthreads();
    {
        float* op = out + 1 + (size_t)base * GMM_D;
        const int limit = min(PPB, T - base) * GMM_D;
        for (int i = tid; i < limit; i += TPB)
            op[i] = stg[(i >> 4) * 17 + (i & 15)];
    }

    // deterministic block reduction + fused finalize
    sRed[tid] = llsum;
    __syncthreads();
    #pragma unroll
    for (int s = TPB / 2; s > 0; s >>= 1) {
        if (tid < s) sRed[tid] += sRed[tid + s];
        __syncthreads();
    }
    if (tid == 0) {
        g_part[blockIdx.x] = sRed[0];
        __threadfence();
        unsigned old = atomicAdd(&g_count, 1u);
        sLast = (old == (unsigned)(gridDim.x - 1));
    }
    __syncthreads();
    if (sLast) {
        __threadfence();
        float acc3 = 0.0f;
        for (int i = tid; i < (int)gridDim.x; i += TPB) acc3 += g_part[i];
        sRed[tid] = acc3;
        __syncthreads();
        #pragma unroll
        for (int s = TPB / 2; s > 0; s >>= 1) {
            if (tid < s) sRed[tid] += sRed[tid + s];
            __syncthreads();
        }
        if (tid == 0) {
            out[0] = sRed[0] * invT;
            g_count = 0;
        }
    }
}

extern "C" void kernel_launch(void* const* d_in, const int* in_sizes, int n_in,
                              void* d_out, int out_size) {
    const float* data  = (const float*)d_in[0];
    const float* wghts = (const float*)d_in[1];
    const float* means = (const float*)d_in[2];
    const float* dcovs = (const float*)d_in[3];
    float* out = (float*)d_out;

    const int T = in_sizes[0] / GMM_D;
    const int grid = (T + PPB - 1) / PPB;

    gmm_precompute<<<1, 1024>>>(wghts, means, dcovs);
    cudaFuncSetAttribute(gmm_main, cudaFuncAttributeMaxDynamicSharedMemorySize, DSMEM);
    gmm_main<<<grid, TPB, DSMEM>>>(data, out, T, 1.0f / (float)T);
}

// round 14
// speedup vs baseline: 1.3301x; 1.2002x over previous
#include <cuda_runtime.h>
#include <cuda_fp16.h>
#include <cstdint>

#define GMM_M  64
#define GMM_D  16
#define TPB    128
#define PPB    128
#define PF1    104              // stage-1 K pitch in halves (208 B, conflict-free)
#define PF1B   208
#define PF2    72               // stage-2 K pitch in halves (144 B, conflict-free)
#define PF2B   144

// static SMEM layout (43392 B < 48 K)
#define OFF_W1 0                                  // [64][PF1]  = 13312 B
#define OFF_W2 13312                              // [24][PF2]  = 3456 B
#define OFF_F  16768                              // [128][PF1] = 26624 B
#define OFF_STG OFF_F                             // f32[128*17] overlays F
#define SMEM_SZ 43392

#define LOG2E  1.4426950408889634f
#define LN2F   0.6931471805599453f

__device__ __align__(16) __half g_W1h[GMM_M * PF1];
__device__ __align__(16) __half g_W2h[24 * PF2];
__device__ float    g_part[8192];
__device__ unsigned g_count = 0;

// ---------------- helpers ----------------
__device__ __forceinline__ uint32_t smem_u32(const void* p) {
    uint32_t a;
    asm("{ .reg .u64 t; cvta.to.shared.u64 t, %1; cvt.u32.u64 %0, t; }" : "=r"(a) : "l"(p));
    return a;
}
__device__ __forceinline__ float ex2f(float x) {
    float r; asm("ex2.approx.f32 %0, %1;" : "=f"(r) : "f"(x)); return r;
}
__device__ __forceinline__ uint32_t h2u(__half2 h) { return *reinterpret_cast<uint32_t*>(&h); }

__device__ __forceinline__ void ldsm4(uint32_t* r, uint32_t addr) {
    asm volatile("ldmatrix.sync.aligned.m8n8.x4.shared.b16 {%0,%1,%2,%3}, [%4];"
        : "=r"(r[0]), "=r"(r[1]), "=r"(r[2]), "=r"(r[3]) : "r"(addr));
}
__device__ __forceinline__ void ldsm2(uint32_t* r, uint32_t addr) {
    asm volatile("ldmatrix.sync.aligned.m8n8.x2.shared.b16 {%0,%1}, [%2];"
        : "=r"(r[0]), "=r"(r[1]) : "r"(addr));
}
__device__ __forceinline__ void mma16816(float* d, const uint32_t* a, const uint32_t* b) {
    asm volatile("mma.sync.aligned.m16n8k16.row.col.f32.f16.f16.f32 "
        "{%0,%1,%2,%3}, {%4,%5,%6,%7}, {%8,%9}, {%0,%1,%2,%3};"
        : "+f"(d[0]), "+f"(d[1]), "+f"(d[2]), "+f"(d[3])
        : "r"(a[0]), "r"(a[1]), "r"(a[2]), "r"(a[3]), "r"(b[0]), "r"(b[1]));
}

// ---------------- kernel 1: build fp16 W images ----------------
// W1 row m: [0-15]=A_h [16-31]=B_h [32]=C_h | [48-63]=A_l [64-79]=B_l [80]=C_l
// W2 row d (<16): k=m -> mu_h ; row 16: ones (likes) ; rows 17-23: zero
__global__ void __launch_bounds__(1024)
gmm_precompute(const float* __restrict__ wghts,
               const float* __restrict__ means,
               const float* __restrict__ dcovs) {
    const int tid = threadIdx.x;
    const __half hz = __float2half_rn(0.0f);
    for (int i = tid; i < GMM_M * PF1; i += 1024) g_W1h[i] = hz;
    for (int i = tid; i < 24 * PF2; i += 1024)    g_W2h[i] = hz;
    __syncthreads();

    const int m = tid >> 4;
    const int d = tid & 15;

    const float dc   = dcovs[m * GMM_D + d];
    const float mu   = means[m * GMM_D + d];
    const float prec = 1.0f / dc;
    const float A = -0.5f * prec * LOG2E;
    const float B = prec * mu * LOG2E;

    float cpart = (-0.5f * prec * mu * mu - 0.5f * __logf(dc)) * LOG2E;
    #pragma unroll
    for (int o = 8; o > 0; o >>= 1)
        cpart += __shfl_down_sync(0xffffffffu, cpart, o, 16);

    const __half Ah = __float2half_rn(A);
    const __half Al = __float2half_rn(A - __half2float(Ah));
    const __half Bh = __float2half_rn(B);
    const __half Bl = __float2half_rn(B - __half2float(Bh));

    __half* w1 = g_W1h + m * PF1;
    w1[d]      = Ah;  w1[16 + d] = Bh;
    w1[48 + d] = Al;  w1[64 + d] = Bl;

    if (d == 0) {
        const float C = cpart + (__logf(wghts[m]) - 8.0f * __logf(6.283185307f)) * LOG2E;
        const __half Ch = __float2half_rn(C);
        w1[32] = Ch;
        w1[80] = __float2half_rn(C - __half2float(Ch));
    }

    g_W2h[d * PF2 + m] = __float2half_rn(mu);
    if (tid < GMM_M) g_W2h[16 * PF2 + tid] = __float2half_rn(1.0f);   // likes row
}

// ---------------- kernel 2: fp16 mma.sync GMM E-step ----------------
__global__ void __launch_bounds__(TPB)
gmm_main(const float* __restrict__ data,
         float* __restrict__ out,
         int T, float invT) {
    __shared__ __align__(16) char dsm[SMEM_SZ];
    __shared__ float sRed[TPB];
    __shared__ bool  sLast;

    const int tid  = threadIdx.x;
    const int lane = tid & 31;
    const int wid  = tid >> 5;
    const uint32_t sb = smem_u32(dsm);

    // copy W images into SMEM
    {
        const float4* s1 = (const float4*)g_W1h;
        float4*       d1 = (float4*)(dsm + OFF_W1);
        for (int i = tid; i < (GMM_M * PF1 * 2) / 16; i += TPB) d1[i] = s1[i];
        const float4* s2 = (const float4*)g_W2h;
        float4*       d2 = (float4*)(dsm + OFF_W2);
        for (int i = tid; i < (24 * PF2 * 2) / 16; i += TPB) d2[i] = s2[i];
    }

    // features for my point -> F row:
    // segA k0-15 x2_h, k16-31 x_h, k32 = 1 | segB k48-63 x2_l, k64-79 x_l, k80+ = 0
    const int  base  = blockIdx.x * PPB;
    const int  tglob = base + tid;
    const bool valid = (tglob < T);
    float xv[GMM_D];
    if (valid) {
        const float4* dp = (const float4*)(data + (size_t)tglob * GMM_D);
        #pragma unroll
        for (int q = 0; q < 4; q++) {
            const float4 f = dp[q];
            xv[4*q] = f.x; xv[4*q+1] = f.y; xv[4*q+2] = f.z; xv[4*q+3] = f.w;
        }
    } else {
        #pragma unroll
        for (int d = 0; d < GMM_D; d++) xv[d] = 0.0f;
    }
    {
        uint32_t row[PF1 / 2];
        #pragma unroll
        for (int j = 0; j < PF1 / 2; j++) row[j] = 0u;
        #pragma unroll
        for (int q = 0; q < 8; q++) {
            const float u0 = xv[2*q] * xv[2*q], u1 = xv[2*q+1] * xv[2*q+1];
            const __half2 uh2 = __floats2half2_rn(u0, u1);
            const __half2 vh2 = __floats2half2_rn(xv[2*q], xv[2*q+1]);
            row[q]      = h2u(uh2);
            row[8 + q]  = h2u(vh2);
            row[24 + q] = h2u(__floats2half2_rn(u0 - __low2float(uh2), u1 - __high2float(uh2)));
            row[32 + q] = h2u(__floats2half2_rn(xv[2*q] - __low2float(vh2),
                                                xv[2*q+1] - __high2float(vh2)));
        }
        row[16] = 0x00003c00u;   // k32 = 1.0h
        uint4* fr = (uint4*)(dsm + OFF_F + tid * PF1B);
        #pragma unroll
        for (int q = 0; q < 13; q++)
            fr[q] = make_uint4(row[4*q], row[4*q+1], row[4*q+2], row[4*q+3]);
    }
    __syncthreads();

    // ---------------- stage 1: E = fh*Wh + fh*Wl + fl*Wh ----------------
    float acc[2][8][4];
    #pragma unroll
    for (int mt = 0; mt < 2; mt++)
        #pragma unroll
        for (int nt = 0; nt < 8; nt++)
            #pragma unroll
            for (int i = 0; i < 4; i++) acc[mt][nt][i] = 0.0f;

    const uint32_t fb  = sb + OFF_F;
    const uint32_t w1b = sb + OFF_W1;
    const int rselA = lane & 15;
    const uint32_t koffA = (lane >> 4) * 16;
    const int nrowB = (lane & 7) + ((lane & 16) ? 8 : 0);
    const uint32_t koffB = (lane & 8) ? 16u : 0u;

    // products 1+2: A from segA (bytes 0..95), B from W_hi (0..95) and W_lo (96..191)
    #pragma unroll
    for (int ks = 0; ks < 3; ks++) {
        uint32_t aF[2][4];
        #pragma unroll
        for (int mt = 0; mt < 2; mt++)
            ldsm4(aF[mt], fb + (wid * 32 + mt * 16 + rselA) * PF1B + ks * 32 + koffA);

        uint32_t bW[8][2];
        #pragma unroll
        for (int p = 0; p < 4; p++) {
            uint32_t r[4];
            ldsm4(r, w1b + (p * 16 + nrowB) * PF1B + ks * 32 + koffB);
            bW[2*p][0] = r[0]; bW[2*p][1] = r[1];
            bW[2*p+1][0] = r[2]; bW[2*p+1][1] = r[3];
        }
        #pragma unroll
        for (int nt = 0; nt < 8; nt++)
            #pragma unroll
            for (int mt = 0; mt < 2; mt++)
                mma16816(acc[mt][nt], aF[mt], bW[nt]);

        #pragma unroll
        for (int p = 0; p < 4; p++) {
            uint32_t r[4];
            ldsm4(r, w1b + (p * 16 + nrowB) * PF1B + 96 + ks * 32 + koffB);
            bW[2*p][0] = r[0]; bW[2*p][1] = r[1];
            bW[2*p+1][0] = r[2]; bW[2*p+1][1] = r[3];
        }
        #pragma unroll
        for (int nt = 0; nt < 8; nt++)
            #pragma unroll
            for (int mt = 0; mt < 2; mt++)
                mma16816(acc[mt][nt], aF[mt], bW[nt]);
    }
    // product 3: A from segB (bytes 96..191), B from W_hi
    #pragma unroll
    for (int ks = 0; ks < 3; ks++) {
        uint32_t aF[2][4];
        #pragma unroll
        for (int mt = 0; mt < 2; mt++)
            ldsm4(aF[mt], fb + (wid * 32 + mt * 16 + rselA) * PF1B + 96 + ks * 32 + koffA);

        uint32_t bW[8][2];
        #pragma unroll
        for (int p = 0; p < 4; p++) {
            uint32_t r[4];
            ldsm4(r, w1b + (p * 16 + nrowB) * PF1B + ks * 32 + koffB);
            bW[2*p][0] = r[0]; bW[2*p][1] = r[1];
            bW[2*p+1][0] = r[2]; bW[2*p+1][1] = r[3];
        }
        #pragma unroll
        for (int nt = 0; nt < 8; nt++)
            #pragma unroll
            for (int mt = 0; mt < 2; mt++)
                mma16816(acc[mt][nt], aF[mt], bW[nt]);
    }

    // ---------------- row-max, exp2, pack p' (hi only) ----------------
    float rA[2], rB[2];
    uint32_t pH[2][8][2];
    #pragma unroll
    for (int mt = 0; mt < 2; mt++) {
        float mg = -1e30f, mg8 = -1e30f;
        #pragma unroll
        for (int nt = 0; nt < 8; nt++) {
            mg  = fmaxf(mg,  fmaxf(acc[mt][nt][0], acc[mt][nt][1]));
            mg8 = fmaxf(mg8, fmaxf(acc[mt][nt][2], acc[mt][nt][3]));
        }
        mg  = fmaxf(mg,  __shfl_xor_sync(0xffffffffu, mg, 1));
        mg  = fmaxf(mg,  __shfl_xor_sync(0xffffffffu, mg, 2));
        mg8 = fmaxf(mg8, __shfl_xor_sync(0xffffffffu, mg8, 1));
        mg8 = fmaxf(mg8, __shfl_xor_sync(0xffffffffu, mg8, 2));
        rA[mt] = mg; rB[mt] = mg8;
        #pragma unroll
        for (int nt = 0; nt < 8; nt++) {
            const float p0 = ex2f(acc[mt][nt][0] - mg);
            const float p1 = ex2f(acc[mt][nt][1] - mg);
            const float p2 = ex2f(acc[mt][nt][2] - mg8);
            const float p3 = ex2f(acc[mt][nt][3] - mg8);
            pH[mt][nt][0] = h2u(__floats2half2_rn(p0, p1));
            pH[mt][nt][1] = h2u(__floats2half2_rn(p2, p3));
        }
    }

    // ---------------- stage 2: [num | like] = P' * W2^T (K=64) ----------------
    float acc2[2][3][4];
    #pragma unroll
    for (int mt = 0; mt < 2; mt++)
        #pragma unroll
        for (int nt = 0; nt < 3; nt++)
            #pragma unroll
            for (int i = 0; i < 4; i++) acc2[mt][nt][i] = 0.0f;

    const uint32_t w2b = sb + OFF_W2;
    #pragma unroll
    for (int ks2 = 0; ks2 < 4; ks2++) {
        uint32_t bW2[3][2];
        {
            uint32_t r[4];
            ldsm4(r, w2b + nrowB * PF2B + ks2 * 32 + koffB);              // ntiles 0,1
            bW2[0][0] = r[0]; bW2[0][1] = r[1];
            bW2[1][0] = r[2]; bW2[1][1] = r[3];
            uint32_t r2[2];
            ldsm2(r2, w2b + (16 + (lane & 7)) * PF2B + ks2 * 32 + koffB); // ntile 2
            bW2[2][0] = r2[0]; bW2[2][1] = r2[1];
        }
        const int nt2 = 2 * ks2;
        #pragma unroll
        for (int mt = 0; mt < 2; mt++) {
            uint32_t a2[4];
            a2[0] = pH[mt][nt2][0];   a2[1] = pH[mt][nt2][1];
            a2[2] = pH[mt][nt2+1][0]; a2[3] = pH[mt][nt2+1][1];
            #pragma unroll
            for (int nt = 0; nt < 3; nt++)
                mma16816(acc2[mt][nt], a2, bW2[nt]);
        }
    }

    // ---------------- epilogue: posteriors, stage, log-likes ----------------
    __syncthreads();    // all warps done reading F -> safe to overlay stg
    float* stg = (float*)(dsm + OFF_STG);
    const int g = lane >> 2, t = lane & 3;
    float llsum = 0.0f;

    #pragma unroll
    for (int mt = 0; mt < 2; mt++) {
        const float likeg  = __shfl_sync(0xffffffffu, acc2[mt][2][0], lane & ~3);
        const float likeg8 = __shfl_sync(0xffffffffu, acc2[mt][2][2], lane & ~3);
        const float invg  = __fdividef(1.0f, likeg);
        const float invg8 = __fdividef(1.0f, likeg8);
        const int r = wid * 32 + mt * 16 + g;
        stg[r * 17 + 2*t]     = acc2[mt][0][0] * invg;
        stg[r * 17 + 2*t + 1] = acc2[mt][0][1] * invg;
        stg[r * 17 + 8 + 2*t] = acc2[mt][1][0] * invg;
        stg[r * 17 + 9 + 2*t] = acc2[mt][1][1] * invg;
        stg[(r+8) * 17 + 2*t]     = acc2[mt][0][2] * invg8;
        stg[(r+8) * 17 + 2*t + 1] = acc2[mt][0][3] * invg8;
        stg[(r+8) * 17 + 8 + 2*t] = acc2[mt][1][2] * invg8;
        stg[(r+8) * 17 + 9 + 2*t] = acc2[mt][1][3] * invg8;
        if (t == 0) {
            if (base + r < T)     llsum += __logf(likeg)  + rA[mt] * LN2F;
            if (base + r + 8 < T) llsum += __logf(likeg8) + rB[mt] * LN2F;
        }
    }
    __syncthreads();
    {
        float* op = out + 1 + (size_t)base * GMM_D;
        const int limit = min(PPB, T - base) * GMM_D;
        for (int i = tid; i < limit; i += TPB)
            op[i] = stg[(i >> 4) * 17 + (i & 15)];
    }

    // deterministic block reduction + fused finalize
    sRed[tid] = llsum;
    __syncthreads();
    #pragma unroll
    for (int s = TPB / 2; s > 0; s >>= 1) {
        if (tid < s) sRed[tid] += sRed[tid + s];
        __syncthreads();
    }
    if (tid == 0) {
        g_part[blockIdx.x] = sRed[0];
        __threadfence();
        unsigned old = atomicAdd(&g_count, 1u);
        sLast = (old == (unsigned)(gridDim.x - 1));
    }
    __syncthreads();
    if (sLast) {
        __threadfence();
        float acc3 = 0.0f;
        for (int i = tid; i < (int)gridDim.x; i += TPB) acc3 += g_part[i];
        sRed[tid] = acc3;
        __syncthreads();
        #pragma unroll
        for (int s = TPB / 2; s > 0; s >>= 1) {
            if (tid < s) sRed[tid] += sRed[tid + s];
            __syncthreads();
        }
        if (tid == 0) {
            out[0] = sRed[0] * invT;
            g_count = 0;
        }
    }
}

extern "C" void kernel_launch(void* const* d_in, const int* in_sizes, int n_in,
                              void* d_out, int out_size) {
    const float* data  = (const float*)d_in[0];
    const float* wghts = (const float*)d_in[1];
    const float* means = (const float*)d_in[2];
    const float* dcovs = (const float*)d_in[3];
    float* out = (float*)d_out;

    const int T = in_sizes[0] / GMM_D;
    const int grid = (T + PPB - 1) / PPB;

    gmm_precompute<<<1, 1024>>>(wghts, means, dcovs);
    gmm_main<<<grid, TPB>>>(data, out, T, 1.0f / (float)T);
}

// round 15
// speedup vs baseline: 1.6885x; 1.2695x over previous
#include <cuda_runtime.h>
#include <cuda_fp16.h>
#include <cstdint>

#define GMM_M  64
#define GMM_D  16
#define TPB    128
#define PPB    128
#define PF1    72               // stage-1 K pitch in halves (144 B, conflict-free)
#define PF1B   144
#define PF2    72               // stage-2 K pitch
#define PF2B   144

// static SMEM layout (31360 B)
#define OFF_W1 0                                  // [64][PF1]  = 9216 B
#define OFF_W2 9216                               // [24][PF2]  = 3456 B
#define OFF_C  12672                              // f32[64]    = 256 B
#define OFF_F  12928                              // [128][PF1] = 18432 B
#define OFF_STG OFF_F                             // f32[128*17] overlays F
#define SMEM_SZ 31360

#define LOG2E  1.4426950408889634f
#define LN2F   0.6931471805599453f

__device__ __align__(16) __half g_W1h[GMM_M * PF1];
__device__ __align__(16) __half g_W2h[24 * PF2];
__device__ float    g_Cf[GMM_M];
__device__ float    g_part[8192];
__device__ unsigned g_count = 0;

// ---------------- helpers ----------------
__device__ __forceinline__ uint32_t smem_u32(const void* p) {
    uint32_t a;
    asm("{ .reg .u64 t; cvta.to.shared.u64 t, %1; cvt.u32.u64 %0, t; }" : "=r"(a) : "l"(p));
    return a;
}
__device__ __forceinline__ float ex2f(float x) {
    float r; asm("ex2.approx.f32 %0, %1;" : "=f"(r) : "f"(x)); return r;
}
__device__ __forceinline__ uint32_t h2u(__half2 h) { return *reinterpret_cast<uint32_t*>(&h); }

__device__ __forceinline__ void ldsm4(uint32_t* r, uint32_t addr) {
    asm volatile("ldmatrix.sync.aligned.m8n8.x4.shared.b16 {%0,%1,%2,%3}, [%4];"
        : "=r"(r[0]), "=r"(r[1]), "=r"(r[2]), "=r"(r[3]) : "r"(addr));
}
__device__ __forceinline__ void ldsm2(uint32_t* r, uint32_t addr) {
    asm volatile("ldmatrix.sync.aligned.m8n8.x2.shared.b16 {%0,%1}, [%2];"
        : "=r"(r[0]), "=r"(r[1]) : "r"(addr));
}
__device__ __forceinline__ void mma16816(float* d, const uint32_t* a, const uint32_t* b) {
    asm volatile("mma.sync.aligned.m16n8k16.row.col.f32.f16.f16.f32 "
        "{%0,%1,%2,%3}, {%4,%5,%6,%7}, {%8,%9}, {%0,%1,%2,%3};"
        : "+f"(d[0]), "+f"(d[1]), "+f"(d[2]), "+f"(d[3])
        : "r"(a[0]), "r"(a[1]), "r"(a[2]), "r"(a[3]), "r"(b[0]), "r"(b[1]));
}

// ---------------- kernel 1: build fp16 W images + f32 C ----------------
// W1 row m: k0-15 A_h, k16-31 B_h | k32-47 A_l, k48-63 B_l  (pad 64-71)
// W2 row d (<16): k=m -> mu_h ; row 16: ones (likes) ; rows 17-23: zero
__global__ void __launch_bounds__(1024)
gmm_precompute(const float* __restrict__ wghts,
               const float* __restrict__ means,
               const float* __restrict__ dcovs) {
    const int tid = threadIdx.x;
    const __half hz = __float2half_rn(0.0f);
    for (int i = tid; i < GMM_M * PF1; i += 1024) g_W1h[i] = hz;
    for (int i = tid; i < 24 * PF2; i += 1024)    g_W2h[i] = hz;
    __syncthreads();

    const int m = tid >> 4;
    const int d = tid & 15;

    const float dc   = dcovs[m * GMM_D + d];
    const float mu   = means[m * GMM_D + d];
    const float prec = 1.0f / dc;
    const float A = -0.5f * prec * LOG2E;
    const float B = prec * mu * LOG2E;

    float cpart = (-0.5f * prec * mu * mu - 0.5f * __logf(dc)) * LOG2E;
    #pragma unroll
    for (int o = 8; o > 0; o >>= 1)
        cpart += __shfl_down_sync(0xffffffffu, cpart, o, 16);

    const __half Ah = __float2half_rn(A);
    const __half Bh = __float2half_rn(B);

    __half* w1 = g_W1h + m * PF1;
    w1[d]      = Ah;
    w1[16 + d] = Bh;
    w1[32 + d] = __float2half_rn(A - __half2float(Ah));
    w1[48 + d] = __float2half_rn(B - __half2float(Bh));

    if (d == 0)
        g_Cf[m] = cpart + (__logf(wghts[m]) - 8.0f * __logf(6.283185307f)) * LOG2E;

    g_W2h[d * PF2 + m] = __float2half_rn(mu);
    if (tid < GMM_M) g_W2h[16 * PF2 + tid] = __float2half_rn(1.0f);   // likes row
}

// ---------------- kernel 2: fp16 mma.sync GMM E-step ----------------
__global__ void __launch_bounds__(TPB)
gmm_main(const float* __restrict__ data,
         float* __restrict__ out,
         int T, float invT) {
    __shared__ __align__(16) char dsm[SMEM_SZ];
    __shared__ float sRed[TPB];
    __shared__ bool  sLast;

    const int tid  = threadIdx.x;
    const int lane = tid & 31;
    const int wid  = tid >> 5;
    const uint32_t sb = smem_u32(dsm);

    // copy W images + C into SMEM
    {
        const float4* s1 = (const float4*)g_W1h;
        float4*       d1 = (float4*)(dsm + OFF_W1);
        for (int i = tid; i < (GMM_M * PF1 * 2) / 16; i += TPB) d1[i] = s1[i];
        const float4* s2 = (const float4*)g_W2h;
        float4*       d2 = (float4*)(dsm + OFF_W2);
        for (int i = tid; i < (24 * PF2 * 2) / 16; i += TPB) d2[i] = s2[i];
        if (tid < GMM_M) ((float*)(dsm + OFF_C))[tid] = g_Cf[tid];
    }

    // features for my point -> F row: k0-15 x2_h | k16-31 x_h | k32-47 x2_l | k48-63 x_l
    const int  base  = blockIdx.x * PPB;
    const int  tglob = base + tid;
    const bool valid = (tglob < T);
    float xv[GMM_D];
    if (valid) {
        const float4* dp = (const float4*)(data + (size_t)tglob * GMM_D);
        #pragma unroll
        for (int q = 0; q < 4; q++) {
            const float4 f = dp[q];
            xv[4*q] = f.x; xv[4*q+1] = f.y; xv[4*q+2] = f.z; xv[4*q+3] = f.w;
        }
    } else {
        #pragma unroll
        for (int d = 0; d < GMM_D; d++) xv[d] = 0.0f;
    }
    {
        uint32_t row[PF1 / 2];
        #pragma unroll
        for (int j = 0; j < PF1 / 2; j++) row[j] = 0u;
        #pragma unroll
        for (int q = 0; q < 8; q++) {
            const float u0 = xv[2*q] * xv[2*q], u1 = xv[2*q+1] * xv[2*q+1];
            const __half2 uh2 = __floats2half2_rn(u0, u1);
            const __half2 vh2 = __floats2half2_rn(xv[2*q], xv[2*q+1]);
            row[q]      = h2u(uh2);
            row[8 + q]  = h2u(vh2);
            row[16 + q] = h2u(__floats2half2_rn(u0 - __low2float(uh2), u1 - __high2float(uh2)));
            row[24 + q] = h2u(__floats2half2_rn(xv[2*q] - __low2float(vh2),
                                                xv[2*q+1] - __high2float(vh2)));
        }
        uint4* fr = (uint4*)(dsm + OFF_F + tid * PF1B);
        #pragma unroll
        for (int q = 0; q < 9; q++)
            fr[q] = make_uint4(row[4*q], row[4*q+1], row[4*q+2], row[4*q+3]);
    }
    __syncthreads();

    // ---------------- stage 1: E = fh*Wh + fh*Wl + fl*Wh  (K=32 per term) ----------------
    float acc[2][8][4];
    #pragma unroll
    for (int mt = 0; mt < 2; mt++)
        #pragma unroll
        for (int nt = 0; nt < 8; nt++)
            #pragma unroll
            for (int i = 0; i < 4; i++) acc[mt][nt][i] = 0.0f;

    const uint32_t fb  = sb + OFF_F;
    const uint32_t w1b = sb + OFF_W1;
    const int rselA = lane & 15;
    const uint32_t koffA = (lane >> 4) * 16;
    const int nrowB = (lane & 7) + ((lane & 16) ? 8 : 0);
    const uint32_t koffB = (lane & 8) ? 16u : 0u;

    #pragma unroll
    for (int ks = 0; ks < 2; ks++) {
        uint32_t a1[2][4], a2[2][4];
        #pragma unroll
        for (int mt = 0; mt < 2; mt++) {
            const uint32_t ra = fb + (wid * 32 + mt * 16 + rselA) * PF1B + ks * 32 + koffA;
            ldsm4(a1[mt], ra);
            ldsm4(a2[mt], ra + 64);
        }
        uint32_t bh[8][2], bl[8][2];
        #pragma unroll
        for (int p = 0; p < 4; p++) {
            const uint32_t rb = w1b + (p * 16 + nrowB) * PF1B + ks * 32 + koffB;
            uint32_t r[4];
            ldsm4(r, rb);
            bh[2*p][0] = r[0]; bh[2*p][1] = r[1];
            bh[2*p+1][0] = r[2]; bh[2*p+1][1] = r[3];
            ldsm4(r, rb + 64);
            bl[2*p][0] = r[0]; bl[2*p][1] = r[1];
            bl[2*p+1][0] = r[2]; bl[2*p+1][1] = r[3];
        }
        #pragma unroll
        for (int nt = 0; nt < 8; nt++)
            #pragma unroll
            for (int mt = 0; mt < 2; mt++) {
                mma16816(acc[mt][nt], a1[mt], bh[nt]);
                mma16816(acc[mt][nt], a1[mt], bl[nt]);
                mma16816(acc[mt][nt], a2[mt], bh[nt]);
            }
    }

    // add exact f32 C per mixture (column of the D-fragment)
    {
        const float* sC = (const float*)(dsm + OFF_C);
        const int t = lane & 3;
        #pragma unroll
        for (int nt = 0; nt < 8; nt++) {
            const float c0 = sC[nt * 8 + 2 * t];
            const float c1 = sC[nt * 8 + 2 * t + 1];
            #pragma unroll
            for (int mt = 0; mt < 2; mt++) {
                acc[mt][nt][0] += c0; acc[mt][nt][1] += c1;
                acc[mt][nt][2] += c0; acc[mt][nt][3] += c1;
            }
        }
    }

    // ---------------- row-max, exp2, pack p' (hi only) ----------------
    float rA[2], rB[2];
    uint32_t pH[2][8][2];
    #pragma unroll
    for (int mt = 0; mt < 2; mt++) {
        float mg = -1e30f, mg8 = -1e30f;
        #pragma unroll
        for (int nt = 0; nt < 8; nt++) {
            mg  = fmaxf(mg,  fmaxf(acc[mt][nt][0], acc[mt][nt][1]));
            mg8 = fmaxf(mg8, fmaxf(acc[mt][nt][2], acc[mt][nt][3]));
        }
        mg  = fmaxf(mg,  __shfl_xor_sync(0xffffffffu, mg, 1));
        mg  = fmaxf(mg,  __shfl_xor_sync(0xffffffffu, mg, 2));
        mg8 = fmaxf(mg8, __shfl_xor_sync(0xffffffffu, mg8, 1));
        mg8 = fmaxf(mg8, __shfl_xor_sync(0xffffffffu, mg8, 2));
        rA[mt] = mg; rB[mt] = mg8;
        #pragma unroll
        for (int nt = 0; nt < 8; nt++) {
            const float p0 = ex2f(acc[mt][nt][0] - mg);
            const float p1 = ex2f(acc[mt][nt][1] - mg);
            const float p2 = ex2f(acc[mt][nt][2] - mg8);
            const float p3 = ex2f(acc[mt][nt][3] - mg8);
            pH[mt][nt][0] = h2u(__floats2half2_rn(p0, p1));
            pH[mt][nt][1] = h2u(__floats2half2_rn(p2, p3));
        }
    }

    // ---------------- stage 2: [num | like] = P' * W2^T (K=64) ----------------
    float acc2[2][3][4];
    #pragma unroll
    for (int mt = 0; mt < 2; mt++)
        #pragma unroll
        for (int nt = 0; nt < 3; nt++)
            #pragma unroll
            for (int i = 0; i < 4; i++) acc2[mt][nt][i] = 0.0f;

    const uint32_t w2b = sb + OFF_W2;
    #pragma unroll
    for (int ks2 = 0; ks2 < 4; ks2++) {
        uint32_t bW2[3][2];
        {
            uint32_t r[4];
            ldsm4(r, w2b + nrowB * PF2B + ks2 * 32 + koffB);              // ntiles 0,1
            bW2[0][0] = r[0]; bW2[0][1] = r[1];
            bW2[1][0] = r[2]; bW2[1][1] = r[3];
            uint32_t r2[2];
            ldsm2(r2, w2b + (16 + (lane & 7)) * PF2B + ks2 * 32 + koffB); // ntile 2
            bW2[2][0] = r2[0]; bW2[2][1] = r2[1];
        }
        const int nt2 = 2 * ks2;
        #pragma unroll
        for (int mt = 0; mt < 2; mt++) {
            uint32_t a2[4];
            a2[0] = pH[mt][nt2][0];   a2[1] = pH[mt][nt2][1];
            a2[2] = pH[mt][nt2+1][0]; a2[3] = pH[mt][nt2+1][1];
            #pragma unroll
            for (int nt = 0; nt < 3; nt++)
                mma16816(acc2[mt][nt], a2, bW2[nt]);
        }
    }

    // ---------------- epilogue: posteriors, stage, log-likes ----------------
    __syncthreads();    // all warps done reading F -> safe to overlay stg
    float* stg = (float*)(dsm + OFF_STG);
    const int g = lane >> 2, t = lane & 3;
    float llsum = 0.0f;

    #pragma unroll
    for (int mt = 0; mt < 2; mt++) {
        const float likeg  = __shfl_sync(0xffffffffu, acc2[mt][2][0], lane & ~3);
        const float likeg8 = __shfl_sync(0xffffffffu, acc2[mt][2][2], lane & ~3);
        const float invg  = __fdividef(1.0f, likeg);
        const float invg8 = __fdividef(1.0f, likeg8);
        const int r = wid * 32 + mt * 16 + g;
        stg[r * 17 + 2*t]     = acc2[mt][0][0] * invg;
        stg[r * 17 + 2*t + 1] = acc2[mt][0][1] * invg;
        stg[r * 17 + 8 + 2*t] = acc2[mt][1][0] * invg;
        stg[r * 17 + 9 + 2*t] = acc2[mt][1][1] * invg;
        stg[(r+8) * 17 + 2*t]     = acc2[mt][0][2] * invg8;
        stg[(r+8) * 17 + 2*t + 1] = acc2[mt][0][3] * invg8;
        stg[(r+8) * 17 + 8 + 2*t] = acc2[mt][1][2] * invg8;
        stg[(r+8) * 17 + 9 + 2*t] = acc2[mt][1][3] * invg8;
        if (t == 0) {
            if (base + r < T)     llsum += __logf(likeg)  + rA[mt] * LN2F;
            if (base + r + 8 < T) llsum += __logf(likeg8) + rB[mt] * LN2F;
        }
    }
    __syncthreads();
    {
        float* op = out + 1 + (size_t)base * GMM_D;
        const int limit = min(PPB, T - base) * GMM_D;
        for (int i = tid; i < limit; i += TPB)
            op[i] = stg[(i >> 4) * 17 + (i & 15)];
    }

    // deterministic block reduction + fused finalize
    sRed[tid] = llsum;
    __syncthreads();
    #pragma unroll
    for (int s = TPB / 2; s > 0; s >>= 1) {
        if (tid < s) sRed[tid] += sRed[tid + s];
        __syncthreads();
    }
    if (tid == 0) {
        g_part[blockIdx.x] = sRed[0];
        __threadfence();
        unsigned old = atomicAdd(&g_count, 1u);
        sLast = (old == (unsigned)(gridDim.x - 1));
    }
    __syncthreads();
    if (sLast) {
        __threadfence();
        float acc3 = 0.0f;
        for (int i = tid; i < (int)gridDim.x; i += TPB) acc3 += g_part[i];
        sRed[tid] = acc3;
        __syncthreads();
        #pragma unroll
        for (int s = TPB / 2; s > 0; s >>= 1) {
            if (tid < s) sRed[tid] += sRed[tid + s];
            __syncthreads();
        }
        if (tid == 0) {
            out[0] = sRed[0] * invT;
            g_count = 0;
        }
    }
}

extern "C" void kernel_launch(void* const* d_in, const int* in_sizes, int n_in,
                              void* d_out, int out_size) {
    const float* data  = (const float*)d_in[0];
    const float* wghts = (const float*)d_in[1];
    const float* means = (const float*)d_in[2];
    const float* dcovs = (const float*)d_in[3];
    float* out = (float*)d_out;

    const int T = in_sizes[0] / GMM_D;
    const int grid = (T + PPB - 1) / PPB;

    gmm_precompute<<<1, 1024>>>(wghts, means, dcovs);
    gmm_main<<<grid, TPB>>>(data, out, T, 1.0f / (float)T);
}